// round 15
// baseline (speedup 1.0000x reference)
#include <cuda_runtime.h>
#include <cuda_fp16.h>
#include <cstdint>

#define THREADS 512      // 16 independent warps, 1 CTA/SM, 128-reg cap
#define NW      16
#define ROWS    32       // edges per warp-chunk (m = 2x16)
#define RING    4        // cp.async slab ring depth (power of 2)
#define SLAB_F  24       // slab row stride in floats (96B)
#define SLAB_B  (32 * SLAB_F * 4)   // 3072 B per slab
#define W1_H    120      // W1 fp16 stride (halves)
#define W2_H    72       // W2 fp16 stride (halves)

#define STG_BYTES (NW * RING * SLAB_B)
#define SM_BYTES  (STG_BYTES + 15360 + 4608 + 256 + 128)

__device__ __forceinline__ uint32_t f2_to_h2(float x, float y) {
    __half2 h = __floats2half2_rn(x, y);
    return *(uint32_t*)&h;
}
__device__ __forceinline__ uint32_t s2u(const void* p) {
    uint32_t a;
    asm("{ .reg .u64 t; cvta.to.shared.u64 t, %1; cvt.u32.u64 %0, t; }" : "=r"(a) : "l"(p));
    return a;
}
__device__ __forceinline__ void cp16(uint32_t dst, const void* src, int sz) {
    asm volatile("cp.async.cg.shared.global [%0], [%1], 16, %2;"
                 :: "r"(dst), "l"(src), "r"(sz) : "memory");
}
__device__ __forceinline__ void ldm_x4(uint32_t* r, uint32_t addr) {
    asm volatile("ldmatrix.sync.aligned.m8n8.x4.shared.b16 {%0,%1,%2,%3}, [%4];"
        : "=r"(r[0]), "=r"(r[1]), "=r"(r[2]), "=r"(r[3]) : "r"(addr));
}
__device__ __forceinline__ void mma_f16(float* d, const uint32_t* a, const uint32_t* b) {
    asm volatile(
        "mma.sync.aligned.m16n8k16.row.col.f32.f16.f16.f32 "
        "{%0,%1,%2,%3}, {%4,%5,%6,%7}, {%8,%9}, {%0,%1,%2,%3};"
        : "+f"(d[0]), "+f"(d[1]), "+f"(d[2]), "+f"(d[3])
        : "r"(a[0]), "r"(a[1]), "r"(a[2]), "r"(a[3]), "r"(b[0]), "r"(b[1]));
}
__device__ __forceinline__ void stg_cs_v2(float* p, float x, float y) {
    asm volatile("st.global.cs.v2.f32 [%0], {%1, %2};" :: "l"(p), "f"(x), "f"(y) : "memory");
}

extern "C" __global__ void __launch_bounds__(THREADS, 1)
edge_mlp_ring2(const float* __restrict__ src, const float* __restrict__ dst,
               const float* __restrict__ ea, const float* __restrict__ u,
               const int* __restrict__ batch,
               const float* __restrict__ W1, const float* __restrict__ b1,
               const float* __restrict__ W2, const float* __restrict__ b2,
               float* __restrict__ out, int E, int nchunks)
{
    extern __shared__ char smraw[];
    float*  stg = (float*)smraw;                             // [16][RING][32][SLAB_F]
    __half* w1s = (__half*)(smraw + STG_BYTES);              // [64 n][W1_H k]
    __half* w2s = (__half*)(smraw + STG_BYTES + 15360);      // [32 n][W2_H k]
    float*  b1s = (float*)(smraw + STG_BYTES + 15360 + 4608);
    float*  b2s = b1s + 64;

    const int t    = threadIdx.x;
    const int w    = t >> 5;
    const int lane = t & 31;
    const int gid  = lane >> 2;   // 0..7
    const int ctid = lane & 3;    // 0..3

    // ---- stage W1/W2 [n][k] halves + biases (once per CTA) ----
    {
        const float2* w12 = (const float2*)W1;   // 64*56 float2
        for (int i = t; i < 3584; i += THREADS) {
            int n = i / 56, k2 = i % 56;
            float2 v = w12[i];
            *(uint32_t*)&w1s[n * W1_H + 2 * k2] = f2_to_h2(v.x, v.y);
        }
        const float2* w22 = (const float2*)W2;   // 32*32 float2
        for (int i = t; i < 1024; i += THREADS) {
            int n = i / 32, k2 = i % 32;
            float2 v = w22[i];
            *(uint32_t*)&w2s[n * W2_H + 2 * k2] = f2_to_h2(v.x, v.y);
        }
        if (t < 64) b1s[t] = b1[t];
        if (t >= 64 && t < 96) b2s[t - 64] = b2[t - 64];
    }
    __syncthreads();

    float* wslab = stg + w * (RING * SLAB_B / 4);
    const uint32_t wslab_u = s2u(wslab);
    const uint32_t w1_u    = s2u(w1s);
    const uint32_t w2_u    = s2u(w2s);

    const int np    = ((lane >> 4) & 1) * 8 + (lane & 7);
    const int bkp   = ((lane >> 3) & 1) * 16;
    const int boff1 = np * (W1_H * 2) + bkp;
    const int boff2 = np * (W2_H * 2) + bkp;

    auto stage_slab = [&](int slot, int e0s, int ks) {
        const float* arr = (ks < 2) ? src : (ks < 4) ? dst : ea;
        const int kof = (ks & 1) * 16;
        const uint32_t sbase = wslab_u + (uint32_t)slot * SLAB_B;
        #pragma unroll
        for (int i = 0; i < 4; i++) {
            int s = lane + 32 * i;          // 0..127
            int r = s >> 2, c = s & 3;
            int e = e0s + r;
            int ec = e < E ? e : E - 1;
            cp16(sbase + (uint32_t)(r * (SLAB_F * 4) + c * 16),
                 (const void*)(arr + (size_t)ec * 32 + kof + c * 4),
                 e < E ? 16 : 0);
        }
        asm volatile("cp.async.commit_group;" ::: "memory");
    };

    int ch = blockIdx.x * NW + w;
    const int step = gridDim.x * NW;
    if (ch >= nchunks) return;

    int issue_e0 = ch * ROWS;
    int issue_ks = 0;
    int slot_i   = 0;

    #pragma unroll
    for (int i = 0; i < RING; i++) {
        stage_slab(i, issue_e0, issue_ks);
        if (++issue_ks == 6) { issue_ks = 0; issue_e0 += step * ROWS; }
    }

    int bA[2], bB[2];
    #pragma unroll
    for (int mt = 0; mt < 2; mt++) {
        int eA = ch * ROWS + 16 * mt + gid, eB = eA + 8;
        bA[mt] = __ldg(&batch[eA < E ? eA : E - 1]);
        bB[mt] = __ldg(&batch[eB < E ? eB : E - 1]);
    }

    for (; ch < nchunks; ch += step) {
        const int e0 = ch * ROWS;
        const int nch = ch + step;

        uint32_t au[2][4];
        #pragma unroll
        for (int mt = 0; mt < 2; mt++) {
            float2 a0 = __ldg((const float2*)&u[(size_t)bA[mt] * 16 + 2 * ctid]);
            float2 a1 = __ldg((const float2*)&u[(size_t)bB[mt] * 16 + 2 * ctid]);
            float2 a2 = __ldg((const float2*)&u[(size_t)bA[mt] * 16 + 8 + 2 * ctid]);
            float2 a3 = __ldg((const float2*)&u[(size_t)bB[mt] * 16 + 8 + 2 * ctid]);
            au[mt][0] = f2_to_h2(a0.x, a0.y);
            au[mt][1] = f2_to_h2(a1.x, a1.y);
            au[mt][2] = f2_to_h2(a2.x, a2.y);
            au[mt][3] = f2_to_h2(a3.x, a3.y);
        }
        if (nch < nchunks) {
            #pragma unroll
            for (int mt = 0; mt < 2; mt++) {
                int eA = nch * ROWS + 16 * mt + gid, eB = eA + 8;
                bA[mt] = __ldg(&batch[eA < E ? eA : E - 1]);
                bB[mt] = __ldg(&batch[eB < E ? eB : E - 1]);
            }
        }

        // ===== GEMM1: [32x112] @ [112x64]; ks 0..5 from slab ring, ks 6 = u =====
        float acc[2][8][4];
        #pragma unroll
        for (int mt = 0; mt < 2; mt++)
            #pragma unroll
            for (int nt = 0; nt < 8; nt++)
                #pragma unroll
                for (int q = 0; q < 4; q++) acc[mt][nt][q] = 0.f;

        #pragma unroll
        for (int ks = 0; ks < 6; ks++) {
            asm volatile("cp.async.wait_group %0;" :: "n"(RING - 1) : "memory");
            __syncwarp();

            const float* sl = wslab + slot_i * (SLAB_B / 4);
            uint32_t a[2][4];
            #pragma unroll
            for (int mt = 0; mt < 2; mt++) {
                int r0 = 16 * mt + gid;
                float2 f0 = *(const float2*)&sl[r0 * SLAB_F + 2 * ctid];
                float2 f1 = *(const float2*)&sl[(r0 + 8) * SLAB_F + 2 * ctid];
                float2 f2 = *(const float2*)&sl[r0 * SLAB_F + 2 * ctid + 8];
                float2 f3 = *(const float2*)&sl[(r0 + 8) * SLAB_F + 2 * ctid + 8];
                a[mt][0] = f2_to_h2(f0.x, f0.y);
                a[mt][1] = f2_to_h2(f1.x, f1.y);
                a[mt][2] = f2_to_h2(f2.x, f2.y);
                a[mt][3] = f2_to_h2(f3.x, f3.y);
            }
            #pragma unroll
            for (int ntp = 0; ntp < 4; ntp++) {
                uint32_t b[4];
                ldm_x4(b, w1_u + 16 * ntp * (W1_H * 2) + boff1 + ks * 32);
                #pragma unroll
                for (int mt = 0; mt < 2; mt++) {
                    mma_f16(acc[mt][2 * ntp],     a[mt], &b[0]);
                    mma_f16(acc[mt][2 * ntp + 1], a[mt], &b[2]);
                }
            }

            __syncwarp();
            stage_slab(slot_i, issue_e0, issue_ks);
            if (++issue_ks == 6) { issue_ks = 0; issue_e0 += step * ROWS; }
            slot_i = (slot_i + 1) & (RING - 1);
        }
        #pragma unroll
        for (int ntp = 0; ntp < 4; ntp++) {
            uint32_t b[4];
            ldm_x4(b, w1_u + 16 * ntp * (W1_H * 2) + boff1 + 6 * 32);
            #pragma unroll
            for (int mt = 0; mt < 2; mt++) {
                mma_f16(acc[mt][2 * ntp],     au[mt], &b[0]);
                mma_f16(acc[mt][2 * ntp + 1], au[mt], &b[2]);
            }
        }

        // ===== fused epilogue1 + GEMM2 =====
        float acc2[2][4][4];
        #pragma unroll
        for (int mt = 0; mt < 2; mt++)
            #pragma unroll
            for (int nt = 0; nt < 4; nt++)
                #pragma unroll
                for (int q = 0; q < 4; q++) acc2[mt][nt][q] = 0.f;

        #pragma unroll
        for (int ks = 0; ks < 4; ks++) {
            float2 bAv = *(const float2*)&b1s[16 * ks + 2 * ctid];
            float2 bBv = *(const float2*)&b1s[16 * ks + 8 + 2 * ctid];
            uint32_t bw[2][4];
            #pragma unroll
            for (int ntp = 0; ntp < 2; ntp++)
                ldm_x4(bw[ntp], w2_u + 16 * ntp * (W2_H * 2) + boff2 + ks * 32);
            #pragma unroll
            for (int mt = 0; mt < 2; mt++) {
                uint32_t a2[4];
                a2[0] = f2_to_h2(fmaxf(acc[mt][2*ks][0] + bAv.x, 0.f),
                                 fmaxf(acc[mt][2*ks][1] + bAv.y, 0.f));
                a2[1] = f2_to_h2(fmaxf(acc[mt][2*ks][2] + bAv.x, 0.f),
                                 fmaxf(acc[mt][2*ks][3] + bAv.y, 0.f));
                a2[2] = f2_to_h2(fmaxf(acc[mt][2*ks+1][0] + bBv.x, 0.f),
                                 fmaxf(acc[mt][2*ks+1][1] + bBv.y, 0.f));
                a2[3] = f2_to_h2(fmaxf(acc[mt][2*ks+1][2] + bBv.x, 0.f),
                                 fmaxf(acc[mt][2*ks+1][3] + bBv.y, 0.f));
                #pragma unroll
                for (int ntp = 0; ntp < 2; ntp++) {
                    mma_f16(acc2[mt][2 * ntp],     a2, &bw[ntp][0]);
                    mma_f16(acc2[mt][2 * ntp + 1], a2, &bw[ntp][2]);
                }
            }
        }

        // ---- epilogue 2: bias + streaming store ----
        #pragma unroll
        for (int mt = 0; mt < 2; mt++) {
            int eA2 = e0 + 16 * mt + gid, eB2 = eA2 + 8;
            #pragma unroll
            for (int nt = 0; nt < 4; nt++) {
                int c = 8 * nt + 2 * ctid;
                float2 bv = *(const float2*)&b2s[c];
                if (eA2 < E)
                    stg_cs_v2(&out[(size_t)eA2 * 32 + c],
                              acc2[mt][nt][0] + bv.x, acc2[mt][nt][1] + bv.y);
                if (eB2 < E)
                    stg_cs_v2(&out[(size_t)eB2 * 32 + c],
                              acc2[mt][nt][2] + bv.x, acc2[mt][nt][3] + bv.y);
            }
        }
    }
}

extern "C" void kernel_launch(void* const* d_in, const int* in_sizes, int n_in,
                              void* d_out, int out_size) {
    const float* src   = (const float*)d_in[0];
    const float* dst   = (const float*)d_in[1];
    const float* ea    = (const float*)d_in[2];
    const float* u     = (const float*)d_in[3];
    const int*   batch = (const int*)d_in[4];
    const float* W1    = (const float*)d_in[5];
    const float* b1    = (const float*)d_in[6];
    const float* W2    = (const float*)d_in[7];
    const float* b2    = (const float*)d_in[8];
    float*       out   = (float*)d_out;

    int E = in_sizes[0] / 32;
    int nchunks = (E + ROWS - 1) / ROWS;

    int nsm = 148;
    cudaDeviceGetAttribute(&nsm, cudaDevAttrMultiProcessorCount, 0);
    int grid = 4 * nsm;                       // finer persistent partitioning -> smaller tail
    int maxg = (nchunks + NW - 1) / NW;
    if (grid > maxg) grid = maxg;

    cudaFuncSetAttribute(edge_mlp_ring2,
                         cudaFuncAttributeMaxDynamicSharedMemorySize, SM_BYTES);
    edge_mlp_ring2<<<grid, THREADS, SM_BYTES>>>(src, dst, ea, u, batch,
                                                W1, b1, W2, b2, out, E, nchunks);
}

// round 16
// speedup vs baseline: 1.0392x; 1.0392x over previous
#include <cuda_runtime.h>
#include <cuda_fp16.h>
#include <cstdint>

#define THREADS 512      // 16 independent warps, 1 CTA/SM, 128-reg cap
#define NW      16
#define ROWS    32       // edges per warp-chunk (m = 2x16)
#define RING    4        // cp.async slab ring depth (power of 2)
#define SLAB_F  24       // slab row stride in floats (96B)
#define SLAB_B  (32 * SLAB_F * 4)   // 3072 B per slab
#define W1_H    120      // W1 fp16 stride (halves)
#define W2_H    72       // W2 fp16 stride (halves)

#define STG_BYTES (NW * RING * SLAB_B)
#define SM_BYTES  (STG_BYTES + 15360 + 4608 + 256 + 128)

__device__ __forceinline__ uint32_t f2_to_h2(float x, float y) {
    __half2 h = __floats2half2_rn(x, y);
    return *(uint32_t*)&h;
}
__device__ __forceinline__ uint32_t s2u(const void* p) {
    uint32_t a;
    asm("{ .reg .u64 t; cvta.to.shared.u64 t, %1; cvt.u32.u64 %0, t; }" : "=r"(a) : "l"(p));
    return a;
}
__device__ __forceinline__ void cp16(uint32_t dst, const void* src, int sz) {
    asm volatile("cp.async.cg.shared.global [%0], [%1], 16, %2;"
                 :: "r"(dst), "l"(src), "r"(sz) : "memory");
}
__device__ __forceinline__ void ldm_x4(uint32_t* r, uint32_t addr) {
    asm volatile("ldmatrix.sync.aligned.m8n8.x4.shared.b16 {%0,%1,%2,%3}, [%4];"
        : "=r"(r[0]), "=r"(r[1]), "=r"(r[2]), "=r"(r[3]) : "r"(addr));
}
__device__ __forceinline__ void mma_f16(float* d, const uint32_t* a, const uint32_t* b) {
    asm volatile(
        "mma.sync.aligned.m16n8k16.row.col.f32.f16.f16.f32 "
        "{%0,%1,%2,%3}, {%4,%5,%6,%7}, {%8,%9}, {%0,%1,%2,%3};"
        : "+f"(d[0]), "+f"(d[1]), "+f"(d[2]), "+f"(d[3])
        : "r"(a[0]), "r"(a[1]), "r"(a[2]), "r"(a[3]), "r"(b[0]), "r"(b[1]));
}

extern "C" __global__ void __launch_bounds__(THREADS, 1)
edge_mlp_ring3(const float* __restrict__ src, const float* __restrict__ dst,
               const float* __restrict__ ea, const float* __restrict__ u,
               const int* __restrict__ batch,
               const float* __restrict__ W1, const float* __restrict__ b1,
               const float* __restrict__ W2, const float* __restrict__ b2,
               float* __restrict__ out, int E, int nchunks)
{
    extern __shared__ char smraw[];
    float*  stg = (float*)smraw;                             // [16][RING][32][SLAB_F]
    __half* w1s = (__half*)(smraw + STG_BYTES);              // [64 n][W1_H k]
    __half* w2s = (__half*)(smraw + STG_BYTES + 15360);      // [32 n][W2_H k]
    float*  b1s = (float*)(smraw + STG_BYTES + 15360 + 4608);
    float*  b2s = b1s + 64;

    const int t    = threadIdx.x;
    const int w    = t >> 5;
    const int lane = t & 31;
    const int gid  = lane >> 2;   // 0..7
    const int ctid = lane & 3;    // 0..3

    // ---- stage W1/W2 [n][k] halves + biases (once per CTA) ----
    {
        const float2* w12 = (const float2*)W1;   // 64*56 float2
        for (int i = t; i < 3584; i += THREADS) {
            int n = i / 56, k2 = i % 56;
            float2 v = w12[i];
            *(uint32_t*)&w1s[n * W1_H + 2 * k2] = f2_to_h2(v.x, v.y);
        }
        const float2* w22 = (const float2*)W2;   // 32*32 float2
        for (int i = t; i < 1024; i += THREADS) {
            int n = i / 32, k2 = i % 32;
            float2 v = w22[i];
            *(uint32_t*)&w2s[n * W2_H + 2 * k2] = f2_to_h2(v.x, v.y);
        }
        if (t < 64) b1s[t] = b1[t];
        if (t >= 64 && t < 96) b2s[t - 64] = b2[t - 64];
    }
    __syncthreads();

    float* wslab = stg + w * (RING * SLAB_B / 4);
    const uint32_t wslab_u = s2u(wslab);
    const uint32_t w1_u    = s2u(w1s);
    const uint32_t w2_u    = s2u(w2s);

    const int np    = ((lane >> 4) & 1) * 8 + (lane & 7);
    const int bkp   = ((lane >> 3) & 1) * 16;
    const int boff1 = np * (W1_H * 2) + bkp;
    const int boff2 = np * (W2_H * 2) + bkp;

    auto stage_slab = [&](int slot, int e0s, int ks) {
        const float* arr = (ks < 2) ? src : (ks < 4) ? dst : ea;
        const int kof = (ks & 1) * 16;
        const uint32_t sbase = wslab_u + (uint32_t)slot * SLAB_B;
        #pragma unroll
        for (int i = 0; i < 4; i++) {
            int s = lane + 32 * i;          // 0..127
            int r = s >> 2, c = s & 3;
            int e = e0s + r;
            int ec = e < E ? e : E - 1;
            cp16(sbase + (uint32_t)(r * (SLAB_F * 4) + c * 16),
                 (const void*)(arr + (size_t)ec * 32 + kof + c * 4),
                 e < E ? 16 : 0);
        }
        asm volatile("cp.async.commit_group;" ::: "memory");
    };

    int ch = blockIdx.x * NW + w;
    const int step = gridDim.x * NW;
    if (ch >= nchunks) return;

    int issue_e0 = ch * ROWS;
    int issue_ks = 0;
    int slot_i   = 0;

    #pragma unroll
    for (int i = 0; i < RING; i++) {
        stage_slab(i, issue_e0, issue_ks);
        if (++issue_ks == 6) { issue_ks = 0; issue_e0 += step * ROWS; }
    }

    int bA[2], bB[2];
    #pragma unroll
    for (int mt = 0; mt < 2; mt++) {
        int eA = ch * ROWS + 16 * mt + gid, eB = eA + 8;
        bA[mt] = batch[eA < E ? eA : E - 1];
        bB[mt] = batch[eB < E ? eB : E - 1];
    }

    for (; ch < nchunks; ch += step) {
        const int e0 = ch * ROWS;
        const int nch = ch + step;

        uint32_t au[2][4];
        #pragma unroll
        for (int mt = 0; mt < 2; mt++) {
            float2 a0 = *(const float2*)&u[(size_t)bA[mt] * 16 + 2 * ctid];
            float2 a1 = *(const float2*)&u[(size_t)bB[mt] * 16 + 2 * ctid];
            float2 a2 = *(const float2*)&u[(size_t)bA[mt] * 16 + 8 + 2 * ctid];
            float2 a3 = *(const float2*)&u[(size_t)bB[mt] * 16 + 8 + 2 * ctid];
            au[mt][0] = f2_to_h2(a0.x, a0.y);
            au[mt][1] = f2_to_h2(a1.x, a1.y);
            au[mt][2] = f2_to_h2(a2.x, a2.y);
            au[mt][3] = f2_to_h2(a3.x, a3.y);
        }
        if (nch < nchunks) {
            #pragma unroll
            for (int mt = 0; mt < 2; mt++) {
                int eA = nch * ROWS + 16 * mt + gid, eB = eA + 8;
                bA[mt] = batch[eA < E ? eA : E - 1];
                bB[mt] = batch[eB < E ? eB : E - 1];
            }
        }

        // ===== GEMM1: [32x112] @ [112x64]; ks 0..5 from slab ring, ks 6 = u =====
        float acc[2][8][4];
        #pragma unroll
        for (int mt = 0; mt < 2; mt++)
            #pragma unroll
            for (int nt = 0; nt < 8; nt++)
                #pragma unroll
                for (int q = 0; q < 4; q++) acc[mt][nt][q] = 0.f;

        #pragma unroll
        for (int ks = 0; ks < 6; ks++) {
            asm volatile("cp.async.wait_group %0;" :: "n"(RING - 1) : "memory");
            __syncwarp();

            const float* sl = wslab + slot_i * (SLAB_B / 4);
            uint32_t a[2][4];
            #pragma unroll
            for (int mt = 0; mt < 2; mt++) {
                int r0 = 16 * mt + gid;
                float2 f0 = *(const float2*)&sl[r0 * SLAB_F + 2 * ctid];
                float2 f1 = *(const float2*)&sl[(r0 + 8) * SLAB_F + 2 * ctid];
                float2 f2 = *(const float2*)&sl[r0 * SLAB_F + 2 * ctid + 8];
                float2 f3 = *(const float2*)&sl[(r0 + 8) * SLAB_F + 2 * ctid + 8];
                a[mt][0] = f2_to_h2(f0.x, f0.y);
                a[mt][1] = f2_to_h2(f1.x, f1.y);
                a[mt][2] = f2_to_h2(f2.x, f2.y);
                a[mt][3] = f2_to_h2(f3.x, f3.y);
            }
            #pragma unroll
            for (int ntp = 0; ntp < 4; ntp++) {
                uint32_t b[4];
                ldm_x4(b, w1_u + 16 * ntp * (W1_H * 2) + boff1 + ks * 32);
                #pragma unroll
                for (int mt = 0; mt < 2; mt++) {
                    mma_f16(acc[mt][2 * ntp],     a[mt], &b[0]);
                    mma_f16(acc[mt][2 * ntp + 1], a[mt], &b[2]);
                }
            }

            __syncwarp();
            stage_slab(slot_i, issue_e0, issue_ks);
            if (++issue_ks == 6) { issue_ks = 0; issue_e0 += step * ROWS; }
            slot_i = (slot_i + 1) & (RING - 1);
        }
        #pragma unroll
        for (int ntp = 0; ntp < 4; ntp++) {
            uint32_t b[4];
            ldm_x4(b, w1_u + 16 * ntp * (W1_H * 2) + boff1 + 6 * 32);
            #pragma unroll
            for (int mt = 0; mt < 2; mt++) {
                mma_f16(acc[mt][2 * ntp],     au[mt], &b[0]);
                mma_f16(acc[mt][2 * ntp + 1], au[mt], &b[2]);
            }
        }

        // ===== fused epilogue1 + GEMM2 =====
        float acc2[2][4][4];
        #pragma unroll
        for (int mt = 0; mt < 2; mt++)
            #pragma unroll
            for (int nt = 0; nt < 4; nt++)
                #pragma unroll
                for (int q = 0; q < 4; q++) acc2[mt][nt][q] = 0.f;

        #pragma unroll
        for (int ks = 0; ks < 4; ks++) {
            float2 bAv = *(const float2*)&b1s[16 * ks + 2 * ctid];
            float2 bBv = *(const float2*)&b1s[16 * ks + 8 + 2 * ctid];
            uint32_t bw[2][4];
            #pragma unroll
            for (int ntp = 0; ntp < 2; ntp++)
                ldm_x4(bw[ntp], w2_u + 16 * ntp * (W2_H * 2) + boff2 + ks * 32);
            #pragma unroll
            for (int mt = 0; mt < 2; mt++) {
                uint32_t a2[4];
                a2[0] = f2_to_h2(fmaxf(acc[mt][2*ks][0] + bAv.x, 0.f),
                                 fmaxf(acc[mt][2*ks][1] + bAv.y, 0.f));
                a2[1] = f2_to_h2(fmaxf(acc[mt][2*ks][2] + bAv.x, 0.f),
                                 fmaxf(acc[mt][2*ks][3] + bAv.y, 0.f));
                a2[2] = f2_to_h2(fmaxf(acc[mt][2*ks+1][0] + bBv.x, 0.f),
                                 fmaxf(acc[mt][2*ks+1][1] + bBv.y, 0.f));
                a2[3] = f2_to_h2(fmaxf(acc[mt][2*ks+1][2] + bBv.x, 0.f),
                                 fmaxf(acc[mt][2*ks+1][3] + bBv.y, 0.f));
                #pragma unroll
                for (int ntp = 0; ntp < 2; ntp++) {
                    mma_f16(acc2[mt][2 * ntp],     a2, &bw[ntp][0]);
                    mma_f16(acc2[mt][2 * ntp + 1], a2, &bw[ntp][2]);
                }
            }
        }

        // ---- epilogue 2: bias + store ----
        #pragma unroll
        for (int mt = 0; mt < 2; mt++) {
            int eA2 = e0 + 16 * mt + gid, eB2 = eA2 + 8;
            #pragma unroll
            for (int nt = 0; nt < 4; nt++) {
                int c = 8 * nt + 2 * ctid;
                float2 bv = *(const float2*)&b2s[c];
                if (eA2 < E) {
                    float2 v;
                    v.x = acc2[mt][nt][0] + bv.x;
                    v.y = acc2[mt][nt][1] + bv.y;
                    *(float2*)&out[(size_t)eA2 * 32 + c] = v;
                }
                if (eB2 < E) {
                    float2 v;
                    v.x = acc2[mt][nt][2] + bv.x;
                    v.y = acc2[mt][nt][3] + bv.y;
                    *(float2*)&out[(size_t)eB2 * 32 + c] = v;
                }
            }
        }
    }
}

extern "C" void kernel_launch(void* const* d_in, const int* in_sizes, int n_in,
                              void* d_out, int out_size) {
    const float* src   = (const float*)d_in[0];
    const float* dst   = (const float*)d_in[1];
    const float* ea    = (const float*)d_in[2];
    const float* u     = (const float*)d_in[3];
    const int*   batch = (const int*)d_in[4];
    const float* W1    = (const float*)d_in[5];
    const float* b1    = (const float*)d_in[6];
    const float* W2    = (const float*)d_in[7];
    const float* b2    = (const float*)d_in[8];
    float*       out   = (float*)d_out;

    int E = in_sizes[0] / 32;
    int nchunks = (E + ROWS - 1) / ROWS;

    int nsm = 148;
    cudaDeviceGetAttribute(&nsm, cudaDevAttrMultiProcessorCount, 0);
    int grid = nsm;                           // exactly one persistent wave (1 CTA/SM)
    int maxg = (nchunks + NW - 1) / NW;
    if (grid > maxg) grid = maxg;

    cudaFuncSetAttribute(edge_mlp_ring3,
                         cudaFuncAttributeMaxDynamicSharedMemorySize, SM_BYTES);
    edge_mlp_ring3<<<grid, THREADS, SM_BYTES>>>(src, dst, ea, u, batch,
                                                W1, b1, W2, b2, out, E, nchunks);
}

// round 17
// speedup vs baseline: 1.0760x; 1.0354x over previous
#include <cuda_runtime.h>
#include <cuda_fp16.h>
#include <cstdint>

#define THREADS 512      // 16 independent warps, 1 CTA/SM, 128-reg cap
#define NW      16
#define ROWS    32       // edges per warp-chunk (m = 2x16)
#define RING    4        // cp.async slab ring depth (power of 2)
#define SLAB_F  24       // slab row stride in floats (96B)
#define SLAB_B  (32 * SLAB_F * 4)   // 3072 B per slab
#define W1_H    120      // W1 fp16 stride (halves)
#define W2_H    72       // W2 fp16 stride (halves)

#define STG_BYTES (NW * RING * SLAB_B)
#define SM_BYTES  (STG_BYTES + 15360 + 4608 + 256 + 128)

__device__ __forceinline__ uint32_t f2_to_h2(float x, float y) {
    __half2 h = __floats2half2_rn(x, y);
    return *(uint32_t*)&h;
}
__device__ __forceinline__ uint32_t s2u(const void* p) {
    uint32_t a;
    asm("{ .reg .u64 t; cvta.to.shared.u64 t, %1; cvt.u32.u64 %0, t; }" : "=r"(a) : "l"(p));
    return a;
}
__device__ __forceinline__ void cp16(uint32_t dst, const void* src) {
    asm volatile("cp.async.cg.shared.global [%0], [%1], 16;"
                 :: "r"(dst), "l"(src) : "memory");
}
__device__ __forceinline__ void cp16p(uint32_t dst, const void* src, int sz) {
    asm volatile("cp.async.cg.shared.global [%0], [%1], 16, %2;"
                 :: "r"(dst), "l"(src), "r"(sz) : "memory");
}
__device__ __forceinline__ void ldm_x4(uint32_t* r, uint32_t addr) {
    asm volatile("ldmatrix.sync.aligned.m8n8.x4.shared.b16 {%0,%1,%2,%3}, [%4];"
        : "=r"(r[0]), "=r"(r[1]), "=r"(r[2]), "=r"(r[3]) : "r"(addr));
}
__device__ __forceinline__ void mma_f16(float* d, const uint32_t* a, const uint32_t* b) {
    asm volatile(
        "mma.sync.aligned.m16n8k16.row.col.f32.f16.f16.f32 "
        "{%0,%1,%2,%3}, {%4,%5,%6,%7}, {%8,%9}, {%0,%1,%2,%3};"
        : "+f"(d[0]), "+f"(d[1]), "+f"(d[2]), "+f"(d[3])
        : "r"(a[0]), "r"(a[1]), "r"(a[2]), "r"(a[3]), "r"(b[0]), "r"(b[1]));
}

extern "C" __global__ void __launch_bounds__(THREADS, 1)
edge_mlp_ring4(const float* __restrict__ src, const float* __restrict__ dst,
               const float* __restrict__ ea, const float* __restrict__ u,
               const int* __restrict__ batch,
               const float* __restrict__ W1, const float* __restrict__ b1,
               const float* __restrict__ W2, const float* __restrict__ b2,
               float* __restrict__ out, int E, int nchunks)
{
    extern __shared__ char smraw[];
    float*  stg = (float*)smraw;                             // [16][RING][32][SLAB_F]
    __half* w1s = (__half*)(smraw + STG_BYTES);              // [64 n][W1_H k]
    __half* w2s = (__half*)(smraw + STG_BYTES + 15360);      // [32 n][W2_H k]
    float*  b1s = (float*)(smraw + STG_BYTES + 15360 + 4608);
    float*  b2s = b1s + 64;

    const int t    = threadIdx.x;
    const int w    = t >> 5;
    const int lane = t & 31;
    const int gid  = lane >> 2;   // 0..7
    const int ctid = lane & 3;    // 0..3

    // ---- stage W1/W2 [n][k] halves + biases (once per CTA) ----
    {
        const float2* w12 = (const float2*)W1;   // 64*56 float2
        for (int i = t; i < 3584; i += THREADS) {
            int n = i / 56, k2 = i % 56;
            float2 v = w12[i];
            *(uint32_t*)&w1s[n * W1_H + 2 * k2] = f2_to_h2(v.x, v.y);
        }
        const float2* w22 = (const float2*)W2;   // 32*32 float2
        for (int i = t; i < 1024; i += THREADS) {
            int n = i / 32, k2 = i % 32;
            float2 v = w22[i];
            *(uint32_t*)&w2s[n * W2_H + 2 * k2] = f2_to_h2(v.x, v.y);
        }
        if (t < 64) b1s[t] = b1[t];
        if (t >= 64 && t < 96) b2s[t - 64] = b2[t - 64];
    }
    __syncthreads();

    float* wslab = stg + w * (RING * SLAB_B / 4);
    const uint32_t wslab_u = s2u(wslab);
    const uint32_t w1_u    = s2u(w1s);
    const uint32_t w2_u    = s2u(w2s);

    const int np    = ((lane >> 4) & 1) * 8 + (lane & 7);
    const int bkp   = ((lane >> 3) & 1) * 16;
    const int boff1 = np * (W1_H * 2) + bkp;
    const int boff2 = np * (W2_H * 2) + bkp;

    // lane-constant staging offsets (hoisted out of all address math)
    const int sl_r = lane >> 2;          // row handled by this lane (+8k per i)
    const int sl_c = lane & 3;           // 16B seg within 64B half-row
    const uint32_t sm_off = (uint32_t)(sl_r * (SLAB_F * 4) + sl_c * 16);
    const int gm_off = sl_r * 32 + sl_c * 4;   // floats

    auto stage_slab = [&](int slot, int e0s, int ks) {
        const float* arr = (ks < 2) ? src : (ks < 4) ? dst : ea;
        const uint32_t sbase = wslab_u + (uint32_t)slot * SLAB_B + sm_off;
        const float* gbase = arr + (size_t)e0s * 32 + (ks & 1) * 16 + gm_off;
        if (e0s + ROWS <= E) {
            // fast path: all rows in bounds; pure strided addresses
            #pragma unroll
            for (int i = 0; i < 4; i++)
                cp16(sbase + (uint32_t)(i * 8 * SLAB_F * 4), gbase + i * 8 * 32);
        } else {
            #pragma unroll
            for (int i = 0; i < 4; i++) {
                int e = e0s + sl_r + 8 * i;
                int ec = e < E ? e : E - 1;
                cp16p(sbase + (uint32_t)(i * 8 * SLAB_F * 4),
                      (const void*)(arr + (size_t)ec * 32 + (ks & 1) * 16 + sl_c * 4),
                      e < E ? 16 : 0);
            }
        }
        asm volatile("cp.async.commit_group;" ::: "memory");
    };

    int ch = blockIdx.x * NW + w;
    const int step = gridDim.x * NW;
    if (ch >= nchunks) return;

    int issue_e0 = ch * ROWS;
    int issue_ks = 0;
    int slot_i   = 0;

    #pragma unroll
    for (int i = 0; i < RING; i++) {
        stage_slab(i, issue_e0, issue_ks);
        if (++issue_ks == 6) { issue_ks = 0; issue_e0 += step * ROWS; }
    }

    int bA[2], bB[2];
    #pragma unroll
    for (int mt = 0; mt < 2; mt++) {
        int eA = ch * ROWS + 16 * mt + gid, eB = eA + 8;
        bA[mt] = batch[eA < E ? eA : E - 1];
        bB[mt] = batch[eB < E ? eB : E - 1];
    }

    for (; ch < nchunks; ch += step) {
        const int e0 = ch * ROWS;
        const int nch = ch + step;

        uint32_t au[2][4];
        #pragma unroll
        for (int mt = 0; mt < 2; mt++) {
            float2 a0 = *(const float2*)&u[(size_t)bA[mt] * 16 + 2 * ctid];
            float2 a1 = *(const float2*)&u[(size_t)bB[mt] * 16 + 2 * ctid];
            float2 a2 = *(const float2*)&u[(size_t)bA[mt] * 16 + 8 + 2 * ctid];
            float2 a3 = *(const float2*)&u[(size_t)bB[mt] * 16 + 8 + 2 * ctid];
            au[mt][0] = f2_to_h2(a0.x, a0.y);
            au[mt][1] = f2_to_h2(a1.x, a1.y);
            au[mt][2] = f2_to_h2(a2.x, a2.y);
            au[mt][3] = f2_to_h2(a3.x, a3.y);
        }
        if (nch < nchunks) {
            #pragma unroll
            for (int mt = 0; mt < 2; mt++) {
                int eA = nch * ROWS + 16 * mt + gid, eB = eA + 8;
                bA[mt] = batch[eA < E ? eA : E - 1];
                bB[mt] = batch[eB < E ? eB : E - 1];
            }
        }

        // ===== GEMM1: [32x112] @ [112x64]; ks 0..5 from slab ring, ks 6 = u =====
        float acc[2][8][4];
        #pragma unroll
        for (int mt = 0; mt < 2; mt++)
            #pragma unroll
            for (int nt = 0; nt < 8; nt++)
                #pragma unroll
                for (int q = 0; q < 4; q++) acc[mt][nt][q] = 0.f;

        #pragma unroll
        for (int ks = 0; ks < 6; ks++) {
            asm volatile("cp.async.wait_group %0;" :: "n"(RING - 1) : "memory");
            __syncwarp();

            const float* sl = wslab + slot_i * (SLAB_B / 4);
            uint32_t a[2][4];
            #pragma unroll
            for (int mt = 0; mt < 2; mt++) {
                int r0 = 16 * mt + gid;
                float2 f0 = *(const float2*)&sl[r0 * SLAB_F + 2 * ctid];
                float2 f1 = *(const float2*)&sl[(r0 + 8) * SLAB_F + 2 * ctid];
                float2 f2 = *(const float2*)&sl[r0 * SLAB_F + 2 * ctid + 8];
                float2 f3 = *(const float2*)&sl[(r0 + 8) * SLAB_F + 2 * ctid + 8];
                a[mt][0] = f2_to_h2(f0.x, f0.y);
                a[mt][1] = f2_to_h2(f1.x, f1.y);
                a[mt][2] = f2_to_h2(f2.x, f2.y);
                a[mt][3] = f2_to_h2(f3.x, f3.y);
            }
            #pragma unroll
            for (int ntp = 0; ntp < 4; ntp++) {
                uint32_t b[4];
                ldm_x4(b, w1_u + 16 * ntp * (W1_H * 2) + boff1 + ks * 32);
                #pragma unroll
                for (int mt = 0; mt < 2; mt++) {
                    mma_f16(acc[mt][2 * ntp],     a[mt], &b[0]);
                    mma_f16(acc[mt][2 * ntp + 1], a[mt], &b[2]);
                }
            }

            __syncwarp();
            stage_slab(slot_i, issue_e0, issue_ks);
            if (++issue_ks == 6) { issue_ks = 0; issue_e0 += step * ROWS; }
            slot_i = (slot_i + 1) & (RING - 1);
        }
        #pragma unroll
        for (int ntp = 0; ntp < 4; ntp++) {
            uint32_t b[4];
            ldm_x4(b, w1_u + 16 * ntp * (W1_H * 2) + boff1 + 6 * 32);
            #pragma unroll
            for (int mt = 0; mt < 2; mt++) {
                mma_f16(acc[mt][2 * ntp],     au[mt], &b[0]);
                mma_f16(acc[mt][2 * ntp + 1], au[mt], &b[2]);
            }
        }

        // ===== fused epilogue1 + GEMM2 =====
        float acc2[2][4][4];
        #pragma unroll
        for (int mt = 0; mt < 2; mt++)
            #pragma unroll
            for (int nt = 0; nt < 4; nt++)
                #pragma unroll
                for (int q = 0; q < 4; q++) acc2[mt][nt][q] = 0.f;

        #pragma unroll
        for (int ks = 0; ks < 4; ks++) {
            float2 bAv = *(const float2*)&b1s[16 * ks + 2 * ctid];
            float2 bBv = *(const float2*)&b1s[16 * ks + 8 + 2 * ctid];
            uint32_t bw[2][4];
            #pragma unroll
            for (int ntp = 0; ntp < 2; ntp++)
                ldm_x4(bw[ntp], w2_u + 16 * ntp * (W2_H * 2) + boff2 + ks * 32);
            #pragma unroll
            for (int mt = 0; mt < 2; mt++) {
                uint32_t a2[4];
                a2[0] = f2_to_h2(fmaxf(acc[mt][2*ks][0] + bAv.x, 0.f),
                                 fmaxf(acc[mt][2*ks][1] + bAv.y, 0.f));
                a2[1] = f2_to_h2(fmaxf(acc[mt][2*ks][2] + bAv.x, 0.f),
                                 fmaxf(acc[mt][2*ks][3] + bAv.y, 0.f));
                a2[2] = f2_to_h2(fmaxf(acc[mt][2*ks+1][0] + bBv.x, 0.f),
                                 fmaxf(acc[mt][2*ks+1][1] + bBv.y, 0.f));
                a2[3] = f2_to_h2(fmaxf(acc[mt][2*ks+1][2] + bBv.x, 0.f),
                                 fmaxf(acc[mt][2*ks+1][3] + bBv.y, 0.f));
                #pragma unroll
                for (int ntp = 0; ntp < 2; ntp++) {
                    mma_f16(acc2[mt][2 * ntp],     a2, &bw[ntp][0]);
                    mma_f16(acc2[mt][2 * ntp + 1], a2, &bw[ntp][2]);
                }
            }
        }

        // ---- epilogue 2: bias + store ----
        #pragma unroll
        for (int mt = 0; mt < 2; mt++) {
            int eA2 = e0 + 16 * mt + gid, eB2 = eA2 + 8;
            #pragma unroll
            for (int nt = 0; nt < 4; nt++) {
                int c = 8 * nt + 2 * ctid;
                float2 bv = *(const float2*)&b2s[c];
                if (eA2 < E) {
                    float2 v;
                    v.x = acc2[mt][nt][0] + bv.x;
                    v.y = acc2[mt][nt][1] + bv.y;
                    *(float2*)&out[(size_t)eA2 * 32 + c] = v;
                }
                if (eB2 < E) {
                    float2 v;
                    v.x = acc2[mt][nt][2] + bv.x;
                    v.y = acc2[mt][nt][3] + bv.y;
                    *(float2*)&out[(size_t)eB2 * 32 + c] = v;
                }
            }
        }
    }
}

extern "C" void kernel_launch(void* const* d_in, const int* in_sizes, int n_in,
                              void* d_out, int out_size) {
    const float* src   = (const float*)d_in[0];
    const float* dst   = (const float*)d_in[1];
    const float* ea    = (const float*)d_in[2];
    const float* u     = (const float*)d_in[3];
    const int*   batch = (const int*)d_in[4];
    const float* W1    = (const float*)d_in[5];
    const float* b1    = (const float*)d_in[6];
    const float* W2    = (const float*)d_in[7];
    const float* b2    = (const float*)d_in[8];
    float*       out   = (float*)d_out;

    int E = in_sizes[0] / 32;
    int nchunks = (E + ROWS - 1) / ROWS;

    int nsm = 148;
    cudaDeviceGetAttribute(&nsm, cudaDevAttrMultiProcessorCount, 0);
    int grid = nsm;                           // exactly one persistent wave (1 CTA/SM)
    int maxg = (nchunks + NW - 1) / NW;
    if (grid > maxg) grid = maxg;

    cudaFuncSetAttribute(edge_mlp_ring4,
                         cudaFuncAttributeMaxDynamicSharedMemorySize, SM_BYTES);
    edge_mlp_ring4<<<grid, THREADS, SM_BYTES>>>(src, dst, ea, u, batch,
                                                W1, b1, W2, b2, out, E, nchunks);
}